// round 6
// baseline (speedup 1.0000x reference)
#include <cuda_runtime.h>
#include <cuda_bf16.h>
#include <cstdint>

// ---------------------------------------------------------------------------
// 2-layer LSTM, B=64, S=512, I=64, H=512, fc head on final h1.
// 64 persistent CTAs x 256 threads. wg0 = layer0 (K=576, 9 chunks),
// wg1 = layer1 (K=1024, 16 chunks). NO grid barrier: producer flags
// g_f0/g_f1 + dataflow waits. h ring-buffered 4 deep so wg0 runs ahead;
// wg1 overlaps its peer-sync with the h0 half of its GEMM.
// bf16 mma.m16n8k16, fp32 accumulate, weights + A-ring in SMEM.
// ---------------------------------------------------------------------------

#define NC    64
#define NTHR  256
#define BSZ   64
#define SEQ   512

#define AROWW 64                      // words per kp-row in gmem (b dim)
#define ASTR  72                      // padded words per kp-row in SMEM
#define CHKP  32                      // kp-rows per chunk
#define SLOTW (CHKP*ASTR)             // 2304 words per slot
#define NSLOT 4
#define WSTR  40                      // sW padded words per kp-row

#define KP0   288                     // layer0 K/2
#define KP1   512                     // layer1 K/2
#define NCH0  9
#define NCH1  16

#define SW0_OFF   0
#define SW1_OFF   (KP0*WSTR)
#define SBIAS_OFF (SW1_OFF + KP1*WSTR)
#define SA_OFF    (SBIAS_OFF + 64)
#define SMEM_WORDS (SA_OFF + 2*NSLOT*SLOTW)
#define SMEM_BYTES (SMEM_WORDS*4)             // 201984

// persistent state (device globals; allocation forbidden)
__device__ uint32_t g_xw[SEQ*32*BSZ];     // [t][kp<32][b] bf16x2
__device__ uint32_t g_h0w[4][256*BSZ];    // 4-deep ring [kp][b]
__device__ uint32_t g_h1w[4][256*BSZ];
__device__ unsigned g_f0[64];             // wg0 producer flags, monotone
__device__ unsigned g_f1[64];             // wg1 producer flags, monotone

__device__ __forceinline__ uint32_t packbf2(float lo, float hi) {
    uint32_t r;
    asm("cvt.rn.bf16x2.f32 %0, %1, %2;" : "=r"(r) : "f"(hi), "f"(lo));
    return r;
}

__device__ __forceinline__ void mma16(float (&d)[4],
                                      uint32_t a0, uint32_t a1, uint32_t a2, uint32_t a3,
                                      uint32_t b0, uint32_t b1) {
    asm volatile(
        "mma.sync.aligned.m16n8k16.row.col.f32.bf16.bf16.f32 "
        "{%0,%1,%2,%3}, {%4,%5,%6,%7}, {%8,%9}, {%0,%1,%2,%3};"
        : "+f"(d[0]), "+f"(d[1]), "+f"(d[2]), "+f"(d[3])
        : "r"(a0), "r"(a1), "r"(a2), "r"(a3), "r"(b0), "r"(b1));
}

__device__ __forceinline__ float fast_tanh(float x) {
    float r;
    asm("tanh.approx.f32 %0, %1;" : "=f"(r) : "f"(x));
    return r;
}
__device__ __forceinline__ float sigm(float x) {
    return 0.5f * fast_tanh(0.5f * x) + 0.5f;
}

__device__ __forceinline__ void cpa16(uint32_t d, const uint32_t* s) {
    asm volatile("cp.async.cg.shared.global [%0], [%1], 16;" :: "r"(d), "l"(s) : "memory");
}
#define CP_COMMIT() asm volatile("cp.async.commit_group;" ::: "memory")
#define CP_WAIT3()  asm volatile("cp.async.wait_group 3;" ::: "memory")
#define BAR_WG(id)  asm volatile("bar.sync %0, 128;" :: "r"(id) : "memory")

// warp-group wait: 64 pollers, then wg-wide named barrier
__device__ __forceinline__ void wg_wait(volatile unsigned* flags, unsigned target,
                                        int tid7, int barid) {
    if (tid7 < 64) {
        volatile unsigned* f = &flags[tid7];
        while ((int)(*f - target) < 0) __nanosleep(20);
    }
    BAR_WG(barid);
}

// warp-group post: wg stores done -> fence -> flag
__device__ __forceinline__ void wg_post(unsigned* flag, unsigned val,
                                        int tid7, int barid) {
    BAR_WG(barid);
    if (tid7 == 0) {
        __threadfence();
        *(volatile unsigned*)flag = val;
    }
}

__device__ __forceinline__ void issue_chunk(const uint32_t* __restrict__ src,
                                            uint32_t dstAdr) {
    cpa16(dstAdr,      src);
    cpa16(dstAdr + 16, src + 4);
    cpa16(dstAdr + 32, src + 8);
    cpa16(dstAdr + 48, src + 12);
}

__global__ void __launch_bounds__(NTHR, 1)
lstm_persist(const float* __restrict__ W0, const float* __restrict__ b0,
             const float* __restrict__ W1, const float* __restrict__ b1,
             const float* __restrict__ Wfc, const float* __restrict__ bfc,
             float* __restrict__ out) {
    extern __shared__ uint32_t sm[];
    float* sBias = (float*)(sm + SBIAS_OFF);

    const int cta  = blockIdx.x;
    const int tid  = threadIdx.x;
    const int n0   = cta * 8;
    const int lane = tid & 31, wrp = tid >> 5;
    const int wrp4 = wrp & 3;
    const int wl   = wrp >> 2;                 // 0 = layer0, 1 = layer1
    const int g    = lane >> 2, t4 = lane & 3;
    const int rowa = wrp4 * 16 + g;

    const int tid7 = tid & 127;
    const int ldr  = tid7 >> 2;
    const int ldc  = (tid7 & 3) * 16;
    const int thrOff = ldr * AROWW + ldc;

    const int barid = 1 + wl;
    const uint32_t saWgAdr = (uint32_t)__cvta_generic_to_shared(sm)
                           + (SA_OFF + wl * NSLOT * SLOTW) * 4
                           + (ldr * ASTR + ldc) * 4;
    const uint32_t* sAwg = sm + SA_OFF + wl * NSLOT * SLOTW;
    const uint32_t* sWl  = sm + (wl ? SW1_OFF : SW0_OFF);
    const int biasOff = wl * 32;
    const int kpIdx = cta * 4 + t4;

    const unsigned base = g_f0[cta];   // == g_f1[cta] at entry, monotone

    // ---- prologue: zero slot-3 h rings (h(-1) reads) ----
    for (int e = cta * NTHR + tid; e < 256 * BSZ; e += NC * NTHR) {
        g_h0w[3][e] = 0u;
        g_h1w[3][e] = 0u;
    }

    // ---- prologue: weights -> SMEM as bf16x2 ----
    for (int e = tid; e < KP0 * 32; e += NTHR) {
        int kp = e >> 5, c = e & 31;
        int q = c >> 3, j = c & 7;
        const float* w = W0 + (2 * kp) * 2048 + q * 512 + n0 + j;
        sm[SW0_OFF + kp * WSTR + c] = packbf2(w[0], w[2048]);
    }
    for (int e = tid; e < KP1 * 32; e += NTHR) {
        int kp = e >> 5, c = e & 31;
        int q = c >> 3, j = c & 7;
        const float* w = W1 + (2 * kp) * 2048 + q * 512 + n0 + j;
        sm[SW1_OFF + kp * WSTR + c] = packbf2(w[0], w[2048]);
    }
    if (tid < 64) {
        int l = tid >> 5, c = tid & 31;
        int q = c >> 3, j = c & 7;
        sBias[tid] = (l ? b1 : b0)[q * 512 + n0 + j];
    }

    __syncthreads();
    if (tid == 0) {                    // publish init (zeros visible)
        __threadfence();
        *(volatile unsigned*)&g_f0[cta] = base + 1;
    }

    float creg[4] = {0.f, 0.f, 0.f, 0.f};
    float accb[4][2];
#pragma unroll
    for (int q = 0; q < 4; ++q) {
        accb[q][0] = sBias[biasOff + q * 8 + 2 * t4];
        accb[q][1] = sBias[biasOff + q * 8 + 2 * t4 + 1];
    }

    if (wl == 0) {
        // =============== layer 0: phases p = 0..511, computes t=p ===========
        for (int p = 0; p < SEQ; ++p) {
            const uint32_t* pX = g_xw + p * (32 * BSZ) + thrOff;
            const uint32_t* pH = g_h0w[(p + 3) & 3] + thrOff;   // h0(p-1)

            issue_chunk(pX, saWgAdr);                  // chunk 0 = x (indep)
            CP_COMMIT();
            wg_wait(g_f0, base + 1 + p, tid7, barid);  // h0(p-1) ready
            if (p >= 2)
                wg_wait(g_f1, base + p - 1, tid7, barid);  // ring back-pressure
            issue_chunk(pH,                    saWgAdr + 1 * (SLOTW * 4)); CP_COMMIT();
            issue_chunk(pH + 1 * (CHKP*AROWW), saWgAdr + 2 * (SLOTW * 4)); CP_COMMIT();

            float acc[4][4];
#pragma unroll
            for (int q = 0; q < 4; ++q) {
                acc[q][0] = accb[q][0]; acc[q][1] = accb[q][1];
                acc[q][2] = accb[q][0]; acc[q][3] = accb[q][1];
            }

            for (int c = 0; c < NCH0; ++c) {
                int cn = c + 3;
                if (cn < NCH0)
                    issue_chunk(pH + (cn - 1) * (CHKP * AROWW),
                                saWgAdr + (cn & 3) * (SLOTW * 4));
                CP_COMMIT();
                CP_WAIT3();
                BAR_WG(barid);
                const uint32_t* As = sAwg + (c & 3) * SLOTW;
                const uint32_t* Bs = sWl + (c * CHKP) * WSTR + g;
#pragma unroll
                for (int k16 = 0; k16 < 4; ++k16) {
                    const uint32_t* ap = As + (k16 * 8 + t4) * ASTR;
                    uint32_t a0 = ap[rowa];
                    uint32_t a1 = ap[rowa + 8];
                    uint32_t a2 = ap[4 * ASTR + rowa];
                    uint32_t a3 = ap[4 * ASTR + rowa + 8];
                    const uint32_t* bp = Bs + (k16 * 8 + t4) * WSTR;
#pragma unroll
                    for (int q = 0; q < 4; ++q)
                        mma16(acc[q], a0, a1, a2, a3, bp[q * 8], bp[4 * WSTR + q * 8]);
                }
            }

            uint32_t* hw = g_h0w[p & 3];
            float hv[4];
#pragma unroll
            for (int pr = 0; pr < 4; ++pr) {
                float cn2 = sigm(acc[1][pr]) * creg[pr]
                          + sigm(acc[0][pr]) * fast_tanh(acc[2][pr]);
                creg[pr] = cn2;
                hv[pr] = sigm(acc[3][pr]) * fast_tanh(cn2);
            }
            __stcg(&hw[kpIdx * BSZ + rowa],     packbf2(hv[0], hv[1]));
            __stcg(&hw[kpIdx * BSZ + rowa + 8], packbf2(hv[2], hv[3]));
            wg_post(&g_f0[cta], base + 2 + p, tid7, barid);
        }
        wg_post(&g_f0[cta], base + 2 + SEQ, tid7, barid);  // equalize flags

        // epilogue: cta0 wg0 computes fc after all wg1s finish phase 512
        if (cta == 0) {
            wg_wait(g_f1, base + 2 + SEQ, tid7, barid);
            if (tid7 < BSZ) {
                const uint32_t* h = g_h1w[(SEQ - 1) & 3];
                float s0 = 0.f, s1 = 0.f;
#pragma unroll 4
                for (int kp = 0; kp < 256; ++kp) {
                    uint32_t w = __ldcg(&h[kp * BSZ + tid7]);
                    float lo = __bfloat162float(__ushort_as_bfloat16((unsigned short)(w & 0xFFFF)));
                    float hi = __bfloat162float(__ushort_as_bfloat16((unsigned short)(w >> 16)));
                    s0 += lo * Wfc[2 * kp];
                    s1 += hi * Wfc[2 * kp + 1];
                }
                out[tid7] = s0 + s1 + bfc[0];
            }
        }
    } else {
        // =============== layer 1: phases p = 1..512, computes t=p-1 =========
        wg_post(&g_f1[cta], base + 2, tid7, barid);        // "phase 0" post
        for (int p = 1; p <= SEQ; ++p) {
            const uint32_t* pH0 = g_h0w[(p + 3) & 3] + thrOff;  // h0(p-1)
            const uint32_t* pH1 = g_h1w[(p + 2) & 3] + thrOff;  // h1(p-2)

            wg_wait(g_f0, base + 1 + p, tid7, barid);  // usually already true
            issue_chunk(pH0,                    saWgAdr);                  CP_COMMIT();
            issue_chunk(pH0 + 1 * (CHKP*AROWW), saWgAdr + 1 * (SLOTW*4)); CP_COMMIT();
            issue_chunk(pH0 + 2 * (CHKP*AROWW), saWgAdr + 2 * (SLOTW*4)); CP_COMMIT();

            float acc[4][4];
#pragma unroll
            for (int q = 0; q < 4; ++q) {
                acc[q][0] = accb[q][0]; acc[q][1] = accb[q][1];
                acc[q][2] = accb[q][0]; acc[q][3] = accb[q][1];
            }

            for (int c = 0; c < NCH1; ++c) {
                int cn = c + 3;
                if (cn < NCH1) {
                    if (cn == 8)                       // h1 part: peer sync,
                        wg_wait(g_f1, base + 1 + p, tid7, barid);  // overlapped
                    const uint32_t* src = (cn < 8)
                        ? pH0 + cn * (CHKP * AROWW)
                        : pH1 + (cn - 8) * (CHKP * AROWW);
                    issue_chunk(src, saWgAdr + (cn & 3) * (SLOTW * 4));
                }
                CP_COMMIT();
                CP_WAIT3();
                BAR_WG(barid);
                const uint32_t* As = sAwg + (c & 3) * SLOTW;
                const uint32_t* Bs = sWl + (c * CHKP) * WSTR + g;
#pragma unroll
                for (int k16 = 0; k16 < 4; ++k16) {
                    const uint32_t* ap = As + (k16 * 8 + t4) * ASTR;
                    uint32_t a0 = ap[rowa];
                    uint32_t a1 = ap[rowa + 8];
                    uint32_t a2 = ap[4 * ASTR + rowa];
                    uint32_t a3 = ap[4 * ASTR + rowa + 8];
                    const uint32_t* bp = Bs + (k16 * 8 + t4) * WSTR;
#pragma unroll
                    for (int q = 0; q < 4; ++q)
                        mma16(acc[q], a0, a1, a2, a3, bp[q * 8], bp[4 * WSTR + q * 8]);
                }
            }

            uint32_t* hw = g_h1w[(p - 1) & 3];
            float hv[4];
#pragma unroll
            for (int pr = 0; pr < 4; ++pr) {
                float cn2 = sigm(acc[1][pr]) * creg[pr]
                          + sigm(acc[0][pr]) * fast_tanh(acc[2][pr]);
                creg[pr] = cn2;
                hv[pr] = sigm(acc[3][pr]) * fast_tanh(cn2);
            }
            __stcg(&hw[kpIdx * BSZ + rowa],     packbf2(hv[0], hv[1]));
            __stcg(&hw[kpIdx * BSZ + rowa + 8], packbf2(hv[2], hv[3]));
            wg_post(&g_f1[cta], base + 2 + p, tid7, barid);
        }
    }
}

// x[b][t][i] -> pair-words [t][kp][b]
__global__ void xpose_kernel(const float* __restrict__ x) {
    int idx = blockIdx.x * blockDim.x + threadIdx.x;
    if (idx < SEQ * 32 * BSZ) {
        int b  = idx & 63;
        int kp = (idx >> 6) & 31;
        int t  = idx >> 11;
        const float* xe = x + ((b * SEQ) + t) * 64 + 2 * kp;
        g_xw[idx] = packbf2(xe[0], xe[1]);
    }
}

extern "C" void kernel_launch(void* const* d_in, const int* in_sizes, int n_in,
                              void* d_out, int out_size) {
    (void)in_sizes; (void)n_in; (void)out_size;
    const float* x   = (const float*)d_in[0];
    const float* W0  = (const float*)d_in[1];
    const float* b0  = (const float*)d_in[2];
    const float* W1  = (const float*)d_in[3];
    const float* b1  = (const float*)d_in[4];
    const float* Wfc = (const float*)d_in[5];
    const float* bfc = (const float*)d_in[6];
    float* out = (float*)d_out;

    cudaFuncSetAttribute(lstm_persist,
                         cudaFuncAttributeMaxDynamicSharedMemorySize, SMEM_BYTES);

    xpose_kernel<<<(SEQ * 32 * BSZ + 255) / 256, 256>>>(x);
    lstm_persist<<<NC, NTHR, SMEM_BYTES>>>(W0, b0, W1, b1, Wfc, bfc, out);
}

// round 7
// speedup vs baseline: 1.2462x; 1.2462x over previous
#include <cuda_runtime.h>
#include <cuda_bf16.h>
#include <cstdint>

// ---------------------------------------------------------------------------
// 2-layer LSTM, B=64, S=512, I=64, H=512, fc head on final h1.
// 64 persistent CTAs x 256 threads. wg0 = layer0 (9 chunks), wg1 = layer1
// (16 chunks). Dataflow sync via TWO aggregated release counters:
//   g_c0 += 1 per wg0 phase-post (init post included): after all wg0 finish
//          phase p, g_c0 == 64*(p+2).
//   g_c1 += 1 per wg1 phase-post (equalizer post for "phase 0"): after all
//          wg1 finish phase q, g_c1 == 64*(q+1).
// Producers: bar.sync(wg) then one red.release.gpu.add. Waiters: all threads
// spin on ld.acquire.gpu of the single counter word (no sleep, no extra bar).
// Counters reset by exit protocol (g_done) -> replay-safe.
// bf16 mma.m16n8k16 fp32-acc; weights + cp.async A-ring in SMEM; c in regs.
// ---------------------------------------------------------------------------

#define NC    64
#define NTHR  256
#define BSZ   64
#define SEQ   512

#define AROWW 64                      // words per kp-row in gmem (b dim)
#define ASTR  72                      // padded words per kp-row in SMEM
#define CHKP  32                      // kp-rows per chunk
#define SLOTW (CHKP*ASTR)             // 2304 words per slot
#define NSLOT 4
#define WSTR  40                      // sW padded words per kp-row

#define KP0   288                     // layer0 K/2
#define KP1   512                     // layer1 K/2
#define NCH0  9
#define NCH1  16

#define SW0_OFF   0
#define SW1_OFF   (KP0*WSTR)
#define SBIAS_OFF (SW1_OFF + KP1*WSTR)
#define SA_OFF    (SBIAS_OFF + 64)
#define SMEM_WORDS (SA_OFF + 2*NSLOT*SLOTW)
#define SMEM_BYTES (SMEM_WORDS*4)             // 201984

// persistent state (device globals; allocation forbidden)
__device__ uint32_t g_xw[SEQ*32*BSZ];     // [t][kp<32][b] bf16x2
__device__ uint32_t g_h0w[4][256*BSZ];    // 4-deep ring [kp][b]
__device__ uint32_t g_h1w[4][256*BSZ];
__device__ unsigned g_c0;                 // wg0 phase counter (reset at exit)
__device__ unsigned g_c1;                 // wg1 phase counter
__device__ unsigned g_done;               // exit protocol

__device__ __forceinline__ uint32_t packbf2(float lo, float hi) {
    uint32_t r;
    asm("cvt.rn.bf16x2.f32 %0, %1, %2;" : "=r"(r) : "f"(hi), "f"(lo));
    return r;
}

__device__ __forceinline__ void mma16(float (&d)[4],
                                      uint32_t a0, uint32_t a1, uint32_t a2, uint32_t a3,
                                      uint32_t b0, uint32_t b1) {
    asm volatile(
        "mma.sync.aligned.m16n8k16.row.col.f32.bf16.bf16.f32 "
        "{%0,%1,%2,%3}, {%4,%5,%6,%7}, {%8,%9}, {%0,%1,%2,%3};"
        : "+f"(d[0]), "+f"(d[1]), "+f"(d[2]), "+f"(d[3])
        : "r"(a0), "r"(a1), "r"(a2), "r"(a3), "r"(b0), "r"(b1));
}

__device__ __forceinline__ float fast_tanh(float x) {
    float r;
    asm("tanh.approx.f32 %0, %1;" : "=f"(r) : "f"(x));
    return r;
}
__device__ __forceinline__ float sigm(float x) {
    return 0.5f * fast_tanh(0.5f * x) + 0.5f;
}

__device__ __forceinline__ void cpa16(uint32_t d, const uint32_t* s) {
    asm volatile("cp.async.cg.shared.global [%0], [%1], 16;" :: "r"(d), "l"(s) : "memory");
}
#define CP_COMMIT() asm volatile("cp.async.commit_group;" ::: "memory")
#define CP_WAIT3()  asm volatile("cp.async.wait_group 3;" ::: "memory")
#define BAR_WG(id)  asm volatile("bar.sync %0, 128;" :: "r"(id) : "memory")

// spin until *ctr >= tgt (single hot word, acquire loads, warp-coalesced)
__device__ __forceinline__ void wait_ge(unsigned* ctr, unsigned tgt) {
    unsigned v;
    do {
        asm volatile("ld.acquire.gpu.global.u32 %0, [%1];" : "=r"(v) : "l"(ctr));
    } while ((int)(v - tgt) < 0);
}

// wg-wide post: bar orders all wg stores before the single release-add
__device__ __forceinline__ void wg_post(unsigned* ctr, int tid7, int barid) {
    BAR_WG(barid);
    if (tid7 == 0)
        asm volatile("red.release.gpu.global.add.u32 [%0], %1;"
                     :: "l"(ctr), "r"(1u) : "memory");
}

__device__ __forceinline__ void issue_chunk(const uint32_t* __restrict__ src,
                                            uint32_t dstAdr) {
    cpa16(dstAdr,      src);
    cpa16(dstAdr + 16, src + 4);
    cpa16(dstAdr + 32, src + 8);
    cpa16(dstAdr + 48, src + 12);
}

__global__ void __launch_bounds__(NTHR, 1)
lstm_persist(const float* __restrict__ W0, const float* __restrict__ b0,
             const float* __restrict__ W1, const float* __restrict__ b1,
             const float* __restrict__ Wfc, const float* __restrict__ bfc,
             float* __restrict__ out) {
    extern __shared__ uint32_t sm[];
    float* sBias = (float*)(sm + SBIAS_OFF);

    const int cta  = blockIdx.x;
    const int tid  = threadIdx.x;
    const int n0   = cta * 8;
    const int lane = tid & 31, wrp = tid >> 5;
    const int wrp4 = wrp & 3;
    const int wl   = wrp >> 2;                 // 0 = layer0, 1 = layer1
    const int g    = lane >> 2, t4 = lane & 3;
    const int rowa = wrp4 * 16 + g;

    const int tid7 = tid & 127;
    const int ldr  = tid7 >> 2;
    const int ldc  = (tid7 & 3) * 16;
    const int thrOff = ldr * AROWW + ldc;

    const int barid = 1 + wl;
    const uint32_t saWgAdr = (uint32_t)__cvta_generic_to_shared(sm)
                           + (SA_OFF + wl * NSLOT * SLOTW) * 4
                           + (ldr * ASTR + ldc) * 4;
    const uint32_t* sAwg = sm + SA_OFF + wl * NSLOT * SLOTW;
    const uint32_t* sWl  = sm + (wl ? SW1_OFF : SW0_OFF);
    const int biasOff = wl * 32;
    const int kpIdx = cta * 4 + t4;

    // ---- prologue: zero slot-3 h rings (h(-1) reads) ----
    for (int e = cta * NTHR + tid; e < 256 * BSZ; e += NC * NTHR) {
        g_h0w[3][e] = 0u;
        g_h1w[3][e] = 0u;
    }

    // ---- prologue: weights -> SMEM as bf16x2 ----
    for (int e = tid; e < KP0 * 32; e += NTHR) {
        int kp = e >> 5, c = e & 31;
        int q = c >> 3, j = c & 7;
        const float* w = W0 + (2 * kp) * 2048 + q * 512 + n0 + j;
        sm[SW0_OFF + kp * WSTR + c] = packbf2(w[0], w[2048]);
    }
    for (int e = tid; e < KP1 * 32; e += NTHR) {
        int kp = e >> 5, c = e & 31;
        int q = c >> 3, j = c & 7;
        const float* w = W1 + (2 * kp) * 2048 + q * 512 + n0 + j;
        sm[SW1_OFF + kp * WSTR + c] = packbf2(w[0], w[2048]);
    }
    if (tid < 64) {
        int l = tid >> 5, c = tid & 31;
        int q = c >> 3, j = c & 7;
        sBias[tid] = (l ? b1 : b0)[q * 512 + n0 + j];
    }

    __syncthreads();
    if (tid == 0)                       // init post (zeros + weights visible)
        asm volatile("red.release.gpu.global.add.u32 [%0], %1;"
                     :: "l"(&g_c0), "r"(1u) : "memory");

    float creg[4] = {0.f, 0.f, 0.f, 0.f};
    float accb[4][2];
#pragma unroll
    for (int q = 0; q < 4; ++q) {
        accb[q][0] = sBias[biasOff + q * 8 + 2 * t4];
        accb[q][1] = sBias[biasOff + q * 8 + 2 * t4 + 1];
    }

    if (wl == 0) {
        // =============== layer 0: phases p = 0..511, computes t=p ===========
        for (int p = 0; p < SEQ; ++p) {
            const uint32_t* pX = g_xw + p * (32 * BSZ) + thrOff;
            const uint32_t* pH = g_h0w[(p + 3) & 3] + thrOff;   // h0(p-1)

            issue_chunk(pX, saWgAdr);                  // chunk 0 = x (indep)
            CP_COMMIT();
            wait_ge(&g_c0, 64u * (p + 1));             // h0(p-1) ready (all)
            if (p >= 2)
                wait_ge(&g_c1, 64u * (p - 2));         // ring back-pressure
            issue_chunk(pH,                    saWgAdr + 1 * (SLOTW * 4)); CP_COMMIT();
            issue_chunk(pH + 1 * (CHKP*AROWW), saWgAdr + 2 * (SLOTW * 4)); CP_COMMIT();

            float acc[4][4];
#pragma unroll
            for (int q = 0; q < 4; ++q) {
                acc[q][0] = accb[q][0]; acc[q][1] = accb[q][1];
                acc[q][2] = accb[q][0]; acc[q][3] = accb[q][1];
            }

            for (int c = 0; c < NCH0; ++c) {
                int cn = c + 3;
                if (cn < NCH0)
                    issue_chunk(pH + (cn - 1) * (CHKP * AROWW),
                                saWgAdr + (cn & 3) * (SLOTW * 4));
                CP_COMMIT();
                CP_WAIT3();
                BAR_WG(barid);
                const uint32_t* As = sAwg + (c & 3) * SLOTW;
                const uint32_t* Bs = sWl + (c * CHKP) * WSTR + g;
#pragma unroll
                for (int k16 = 0; k16 < 4; ++k16) {
                    const uint32_t* ap = As + (k16 * 8 + t4) * ASTR;
                    uint32_t a0 = ap[rowa];
                    uint32_t a1 = ap[rowa + 8];
                    uint32_t a2 = ap[4 * ASTR + rowa];
                    uint32_t a3 = ap[4 * ASTR + rowa + 8];
                    const uint32_t* bp = Bs + (k16 * 8 + t4) * WSTR;
#pragma unroll
                    for (int q = 0; q < 4; ++q)
                        mma16(acc[q], a0, a1, a2, a3, bp[q * 8], bp[4 * WSTR + q * 8]);
                }
            }

            uint32_t* hw = g_h0w[p & 3];
            float hv[4];
#pragma unroll
            for (int pr = 0; pr < 4; ++pr) {
                float cn2 = sigm(acc[1][pr]) * creg[pr]
                          + sigm(acc[0][pr]) * fast_tanh(acc[2][pr]);
                creg[pr] = cn2;
                hv[pr] = sigm(acc[3][pr]) * fast_tanh(cn2);
            }
            __stcg(&hw[kpIdx * BSZ + rowa],     packbf2(hv[0], hv[1]));
            __stcg(&hw[kpIdx * BSZ + rowa + 8], packbf2(hv[2], hv[3]));
            wg_post(&g_c0, tid7, barid);               // g_c0 -> 64*(p+2)
        }

        // epilogue: cta0 wg0 computes fc after all wg1s finish phase 512
        if (cta == 0) {
            wait_ge(&g_c1, 64u * (SEQ + 1));
            if (tid7 < BSZ) {
                const uint32_t* h = g_h1w[(SEQ - 1) & 3];
                float s0 = 0.f, s1 = 0.f;
#pragma unroll 4
                for (int kp = 0; kp < 256; ++kp) {
                    uint32_t w = __ldcg(&h[kp * BSZ + tid7]);
                    float lo = __bfloat162float(__ushort_as_bfloat16((unsigned short)(w & 0xFFFF)));
                    float hi = __bfloat162float(__ushort_as_bfloat16((unsigned short)(w >> 16)));
                    s0 += lo * Wfc[2 * kp];
                    s1 += hi * Wfc[2 * kp + 1];
                }
                out[tid7] = s0 + s1 + bfc[0];
            }
        }
    } else {
        // =============== layer 1: phases p = 1..512, computes t=p-1 =========
        wg_post(&g_c1, tid7, barid);                   // equalizer ("phase 0")
        for (int p = 1; p <= SEQ; ++p) {
            const uint32_t* pH0 = g_h0w[(p + 3) & 3] + thrOff;  // h0(p-1)
            const uint32_t* pH1 = g_h1w[(p + 2) & 3] + thrOff;  // h1(p-2)

            wait_ge(&g_c0, 64u * (p + 1));             // h0(p-1) ready (all)
            issue_chunk(pH0,                    saWgAdr);                  CP_COMMIT();
            issue_chunk(pH0 + 1 * (CHKP*AROWW), saWgAdr + 1 * (SLOTW*4)); CP_COMMIT();
            issue_chunk(pH0 + 2 * (CHKP*AROWW), saWgAdr + 2 * (SLOTW*4)); CP_COMMIT();

            float acc[4][4];
#pragma unroll
            for (int q = 0; q < 4; ++q) {
                acc[q][0] = accb[q][0]; acc[q][1] = accb[q][1];
                acc[q][2] = accb[q][0]; acc[q][3] = accb[q][1];
            }

            for (int c = 0; c < NCH1; ++c) {
                int cn = c + 3;
                if (cn < NCH1) {
                    if (cn == 8)                       // h1(p-2) ready (all);
                        wait_ge(&g_c1, 64u * p);       // overlapped w/ chunks 0-4
                    const uint32_t* src = (cn < 8)
                        ? pH0 + cn * (CHKP * AROWW)
                        : pH1 + (cn - 8) * (CHKP * AROWW);
                    issue_chunk(src, saWgAdr + (cn & 3) * (SLOTW * 4));
                }
                CP_COMMIT();
                CP_WAIT3();
                BAR_WG(barid);
                const uint32_t* As = sAwg + (c & 3) * SLOTW;
                const uint32_t* Bs = sWl + (c * CHKP) * WSTR + g;
#pragma unroll
                for (int k16 = 0; k16 < 4; ++k16) {
                    const uint32_t* ap = As + (k16 * 8 + t4) * ASTR;
                    uint32_t a0 = ap[rowa];
                    uint32_t a1 = ap[rowa + 8];
                    uint32_t a2 = ap[4 * ASTR + rowa];
                    uint32_t a3 = ap[4 * ASTR + rowa + 8];
                    const uint32_t* bp = Bs + (k16 * 8 + t4) * WSTR;
#pragma unroll
                    for (int q = 0; q < 4; ++q)
                        mma16(acc[q], a0, a1, a2, a3, bp[q * 8], bp[4 * WSTR + q * 8]);
                }
            }

            uint32_t* hw = g_h1w[(p - 1) & 3];
            float hv[4];
#pragma unroll
            for (int pr = 0; pr < 4; ++pr) {
                float cn2 = sigm(acc[1][pr]) * creg[pr]
                          + sigm(acc[0][pr]) * fast_tanh(acc[2][pr]);
                creg[pr] = cn2;
                hv[pr] = sigm(acc[3][pr]) * fast_tanh(cn2);
            }
            __stcg(&hw[kpIdx * BSZ + rowa],     packbf2(hv[0], hv[1]));
            __stcg(&hw[kpIdx * BSZ + rowa + 8], packbf2(hv[2], hv[3]));
            wg_post(&g_c1, tid7, barid);               // g_c1 -> 64*(p+1)
        }
    }

    // ---- exit protocol: reset counters for the next graph replay ----
    __syncthreads();
    if (tid == 0)
        asm volatile("red.release.gpu.global.add.u32 [%0], %1;"
                     :: "l"(&g_done), "r"(1u) : "memory");
    if (cta == 0 && tid == 0) {
        wait_ge(&g_done, NC);
        *(volatile unsigned*)&g_c0 = 0u;
        *(volatile unsigned*)&g_c1 = 0u;
        *(volatile unsigned*)&g_done = 0u;
    }
}

// x[b][t][i] -> pair-words [t][kp][b]
__global__ void xpose_kernel(const float* __restrict__ x) {
    int idx = blockIdx.x * blockDim.x + threadIdx.x;
    if (idx < SEQ * 32 * BSZ) {
        int b  = idx & 63;
        int kp = (idx >> 6) & 31;
        int t  = idx >> 11;
        const float* xe = x + ((b * SEQ) + t) * 64 + 2 * kp;
        g_xw[idx] = packbf2(xe[0], xe[1]);
    }
}

extern "C" void kernel_launch(void* const* d_in, const int* in_sizes, int n_in,
                              void* d_out, int out_size) {
    (void)in_sizes; (void)n_in; (void)out_size;
    const float* x   = (const float*)d_in[0];
    const float* W0  = (const float*)d_in[1];
    const float* b0  = (const float*)d_in[2];
    const float* W1  = (const float*)d_in[3];
    const float* b1  = (const float*)d_in[4];
    const float* Wfc = (const float*)d_in[5];
    const float* bfc = (const float*)d_in[6];
    float* out = (float*)d_out;

    cudaFuncSetAttribute(lstm_persist,
                         cudaFuncAttributeMaxDynamicSharedMemorySize, SMEM_BYTES);

    xpose_kernel<<<(SEQ * 32 * BSZ + 255) / 256, 256>>>(x);
    lstm_persist<<<NC, NTHR, SMEM_BYTES>>>(W0, b0, W1, b1, Wfc, bfc, out);
}